// round 1
// baseline (speedup 1.0000x reference)
#include <cuda_runtime.h>
#include <math.h>

// MFA E-step: M=32 components, N=8192 points, D=64 dims, K=16 factors.
// Woodbury: Sigma^-1 = Psi^-1 - Psi^-1 L (I + L^T Psi^-1 L)^-1 L^T Psi^-1
//   Mt = I + L^T Psi^-1 L (KxK),  C = chol(Mt)
//   u = C^-1 L^T Psi^-1 diff     (computed as G2 * diffs, diffs = (x-mu)*sqrt(invPsi))
//   maha = sum diffs^2 - |u|^2
//   e_z  = C^-T u
//   term1 = Mt^-1 = C^-T C^-1
//   logdet Sigma = sum log PsiEff + 2 sum log C_kk

#define MCOMP 32
#define NPTS  8192
#define DDIM  64
#define KFAC  16

// ---- scratch (__device__ globals; no allocation allowed) ----
__device__ __align__(16) float g_G2[MCOMP * KFAC * DDIM];   // [m][k][d], row-scaled by s_d
__device__ __align__(16) float g_T[MCOMP * KFAC * KFAC];    // C^-T dense
__device__ __align__(16) float g_t1[MCOMP * KFAC * KFAC];   // Mt^-1
__device__ __align__(16) float g_s[DDIM];                   // sqrt(1/(Psi+1e-6))
__device__ float g_c[MCOMP];                                // log pi - 0.5(D log2pi + logdet)
__device__ __align__(16) float g_logp[NPTS * MCOMP];        // [n][m]

// ============================================================
// Kernel 1: per-component precompute. grid = M blocks, 256 thr
// ============================================================
__global__ __launch_bounds__(256) void precompute_kernel(
    const float* __restrict__ pi,
    const float* __restrict__ Lambda,   // [M][D][K]
    const float* __restrict__ Psi)      // [D]
{
    __shared__ float LamS[DDIM * KFAC];     // [d][k]
    __shared__ float invPsiS[DDIM];
    __shared__ float sS[DDIM];
    __shared__ float MS[KFAC * KFAC];
    __shared__ float CS[KFAC * KFAC];
    __shared__ float CinvS[KFAC * KFAC];

    const int m = blockIdx.x;
    const int tid = threadIdx.x;

    if (tid < DDIM) {
        float pe = Psi[tid] + 1e-6f;
        float ip = 1.0f / pe;
        invPsiS[tid] = ip;
        sS[tid] = sqrtf(ip);
    }
    for (int idx = tid; idx < DDIM * KFAC; idx += 256)
        LamS[idx] = Lambda[m * DDIM * KFAC + idx];
    __syncthreads();

    if (m == 0 && tid < DDIM) g_s[tid] = sS[tid];

    // Mt = I + Lam^T diag(invPsi) Lam
    {
        int i = tid >> 4, j = tid & 15;
        float acc = (i == j) ? 1.0f : 0.0f;
        #pragma unroll 8
        for (int d = 0; d < DDIM; d++)
            acc = fmaf(LamS[d * KFAC + i] * invPsiS[d], LamS[d * KFAC + j], acc);
        MS[tid] = acc;
    }
    __syncthreads();

    // Cholesky of Mt (KxK), lower C
    for (int jj = 0; jj < KFAC; jj++) {
        if (tid == 0) CS[jj * KFAC + jj] = sqrtf(MS[jj * KFAC + jj]);
        __syncthreads();
        if (tid > jj && tid < KFAC)
            CS[tid * KFAC + jj] = MS[tid * KFAC + jj] / CS[jj * KFAC + jj];
        __syncthreads();
        {
            int a = tid >> 4, b = tid & 15;
            if (a > jj && b > jj && b <= a)
                MS[a * KFAC + b] -= CS[a * KFAC + jj] * CS[b * KFAC + jj];
        }
        __syncthreads();
    }

    // Cinv = C^-1 (lower tri), one column per thread
    if (tid < KFAC) {
        int c = tid;
        float x[KFAC];
        #pragma unroll
        for (int i = 0; i < KFAC; i++) {
            float v = (i == c) ? 1.0f : 0.0f;
            for (int k = c; k < i; k++) v -= CS[i * KFAC + k] * x[k];
            x[i] = (i >= c) ? v / CS[i * KFAC + i] : 0.0f;
        }
        #pragma unroll
        for (int i = 0; i < KFAC; i++) CinvS[i * KFAC + c] = x[i];
    }
    __syncthreads();

    // term1 = Cinv^T Cinv ; T = Cinv^T (dense)
    {
        int i = tid >> 4, j = tid & 15;
        float acc = 0.0f;
        #pragma unroll
        for (int k = 0; k < KFAC; k++)
            acc = fmaf(CinvS[k * KFAC + i], CinvS[k * KFAC + j], acc);
        g_t1[m * 256 + tid] = acc;
        g_T[m * 256 + tid] = CinvS[j * KFAC + i];
    }

    // G2[i][d] = (sum_{k<=i} Cinv[i][k] Lam[d][k]) * s_d
    for (int idx = tid; idx < KFAC * DDIM; idx += 256) {
        int i = idx >> 6, d = idx & 63;
        float acc = 0.0f;
        for (int k = 0; k <= i; k++)
            acc = fmaf(CinvS[i * KFAC + k], LamS[d * KFAC + k], acc);
        g_G2[m * KFAC * DDIM + idx] = acc * sS[d];
    }

    if (tid == 0) {
        float logdet = 0.0f;
        for (int d = 0; d < DDIM; d++) logdet += logf(Psi[d] + 1e-6f);
        for (int k = 0; k < KFAC; k++) logdet += 2.0f * logf(CS[k * KFAC + k]);
        const float LOG2PI = 1.8378770664093453f;
        g_c[m] = logf(pi[m] + 1e-10f) - 0.5f * (64.0f * LOG2PI + logdet);
    }
}

// ============================================================
// Kernel 2: main. grid = (N/128, M), 128 threads, 1 point/thread
// ============================================================
__global__ __launch_bounds__(128) void main_kernel(
    const float* __restrict__ X,    // [N][D]
    const float* __restrict__ mu,   // [M][D]
    float* __restrict__ out)
{
    __shared__ float4 Xs4[16 * 129];   // [d4][n], padded rows (33,024 B)
    __shared__ float4 G2s[256];        // [k][d4]
    __shared__ float4 Ts[64];          // [i][j4]
    __shared__ float4 t1s[64];         // [i][j4]
    __shared__ float4 mus[16];
    __shared__ float4 ss4[16];

    const int m = blockIdx.y;
    const int nb = blockIdx.x * 128;
    const int tid = threadIdx.x;

    // per-m constants
    G2s[tid]       = ((const float4*)g_G2)[m * 256 + tid];
    G2s[tid + 128] = ((const float4*)g_G2)[m * 256 + tid + 128];
    if (tid < 64)  Ts[tid]  = ((const float4*)g_T)[m * 64 + tid];
    if (tid >= 64) t1s[tid - 64] = ((const float4*)g_t1)[m * 64 + (tid - 64)];
    if (tid < 16) {
        mus[tid] = ((const float4*)mu)[m * 16 + tid];
        ss4[tid] = ((const float4*)g_s)[tid];
    }
    __syncthreads();

    // stage diffs = (x - mu) * s into smem, transposed-ish [d4][n]
    const float4* Xg = (const float4*)X;
    #pragma unroll
    for (int it = 0; it < 16; it++) {
        int idx = tid + it * 128;          // 0..2047
        int n  = idx >> 4;
        int d4 = idx & 15;
        float4 x = Xg[nb * 16 + idx];      // coalesced: (nb+n)*16 + d4
        float4 mu4 = mus[d4], s4 = ss4[d4];
        float4 r;
        r.x = (x.x - mu4.x) * s4.x;
        r.y = (x.y - mu4.y) * s4.y;
        r.z = (x.z - mu4.z) * s4.z;
        r.w = (x.w - mu4.w) * s4.w;
        Xs4[d4 * 129 + n] = r;
    }
    __syncthreads();

    // u = G2 * diffs ; q = |diffs|^2
    float q = 0.0f;
    float u[KFAC];
    #pragma unroll
    for (int k = 0; k < KFAC; k++) u[k] = 0.0f;

    #pragma unroll 4
    for (int d4 = 0; d4 < 16; d4++) {
        float4 xv = Xs4[d4 * 129 + tid];
        q = fmaf(xv.x, xv.x, q);
        q = fmaf(xv.y, xv.y, q);
        q = fmaf(xv.z, xv.z, q);
        q = fmaf(xv.w, xv.w, q);
        #pragma unroll
        for (int k = 0; k < KFAC; k++) {
            float4 g = G2s[k * 16 + d4];   // broadcast
            u[k] = fmaf(g.x, xv.x, u[k]);
            u[k] = fmaf(g.y, xv.y, u[k]);
            u[k] = fmaf(g.z, xv.z, u[k]);
            u[k] = fmaf(g.w, xv.w, u[k]);
        }
    }

    float uu = 0.0f;
    #pragma unroll
    for (int k = 0; k < KFAC; k++) uu = fmaf(u[k], u[k], uu);
    float maha = q - uu;

    const int n = nb + tid;
    g_logp[n * MCOMP + m] = g_c[m] - 0.5f * maha;

    // e_z = T u
    float ez[KFAC];
    #pragma unroll
    for (int i = 0; i < KFAC; i++) {
        float acc = 0.0f;
        #pragma unroll
        for (int j4 = 0; j4 < 4; j4++) {
            float4 t = Ts[i * 4 + j4];
            acc = fmaf(t.x, u[j4 * 4 + 0], acc);
            acc = fmaf(t.y, u[j4 * 4 + 1], acc);
            acc = fmaf(t.z, u[j4 * 4 + 2], acc);
            acc = fmaf(t.w, u[j4 * 4 + 3], acc);
        }
        ez[i] = acc;
    }

    float4* out4 = (float4*)out;
    const long long pair = (long long)m * NPTS + n;

    // e_z out: base = N*M floats = 65536 float4
    {
        long long b = 65536LL + pair * 4;
        #pragma unroll
        for (int j4 = 0; j4 < 4; j4++) {
            float4 r;
            r.x = ez[j4 * 4 + 0];
            r.y = ez[j4 * 4 + 1];
            r.z = ez[j4 * 4 + 2];
            r.w = ez[j4 * 4 + 3];
            __stcs(&out4[b + j4], r);
        }
    }

    // e_zz out: base = (N*M + M*N*K) floats = 1114112 float4
    {
        long long b = 1114112LL + pair * 64;
        #pragma unroll
        for (int i = 0; i < KFAC; i++) {
            float e = ez[i];
            #pragma unroll
            for (int j4 = 0; j4 < 4; j4++) {
                float4 t1 = t1s[i * 4 + j4];
                float4 r;
                r.x = fmaf(e, ez[j4 * 4 + 0], t1.x);
                r.y = fmaf(e, ez[j4 * 4 + 1], t1.y);
                r.z = fmaf(e, ez[j4 * 4 + 2], t1.z);
                r.w = fmaf(e, ez[j4 * 4 + 3], t1.w);
                __stcs(&out4[b + i * 4 + j4], r);
            }
        }
    }
}

// ============================================================
// Kernel 3: softmax over m -> responsibilities [N][M]
// ============================================================
__global__ __launch_bounds__(256) void softmax_kernel(float* __restrict__ out)
{
    const int n = blockIdx.x * 256 + threadIdx.x;
    if (n >= NPTS) return;
    const float4* lp4 = ((const float4*)g_logp) + n * 8;
    float v[32];
    #pragma unroll
    for (int j = 0; j < 8; j++) {
        float4 a = lp4[j];
        v[j * 4 + 0] = a.x; v[j * 4 + 1] = a.y;
        v[j * 4 + 2] = a.z; v[j * 4 + 3] = a.w;
    }
    float mx = v[0];
    #pragma unroll
    for (int i = 1; i < 32; i++) mx = fmaxf(mx, v[i]);
    float s = 0.0f;
    #pragma unroll
    for (int i = 0; i < 32; i++) { v[i] = __expf(v[i] - mx); s += v[i]; }
    float inv = 1.0f / s;
    float4* o4 = ((float4*)out) + n * 8;
    #pragma unroll
    for (int j = 0; j < 8; j++) {
        float4 r;
        r.x = v[j * 4 + 0] * inv;
        r.y = v[j * 4 + 1] * inv;
        r.z = v[j * 4 + 2] * inv;
        r.w = v[j * 4 + 3] * inv;
        o4[j] = r;
    }
}

// ============================================================
extern "C" void kernel_launch(void* const* d_in, const int* in_sizes, int n_in,
                              void* d_out, int out_size)
{
    (void)in_sizes; (void)n_in; (void)out_size;
    const float* X      = (const float*)d_in[0];   // [N,D]
    const float* pi     = (const float*)d_in[1];   // [M]
    const float* mu     = (const float*)d_in[2];   // [M,D]
    const float* Lambda = (const float*)d_in[3];   // [M,D,K]
    const float* Psi    = (const float*)d_in[4];   // [D]
    float* out = (float*)d_out;

    precompute_kernel<<<MCOMP, 256>>>(pi, Lambda, Psi);
    main_kernel<<<dim3(NPTS / 128, MCOMP), 128>>>(X, mu, out);
    softmax_kernel<<<NPTS / 256, 256>>>(out);
}

// round 2
// speedup vs baseline: 2.3482x; 2.3482x over previous
#include <cuda_runtime.h>
#include <math.h>

// MFA E-step: M=32 components, N=8192 points, D=64 dims, K=16 factors.
// Woodbury: Sigma^-1 = Psi^-1 - Psi^-1 L (I + L^T Psi^-1 L)^-1 L^T Psi^-1
//   Mt = I + L^T Psi^-1 L (KxK),  C = chol(Mt)
//   u = C^-1 L^T Psi^-1 diff   (via G2 * diffs, diffs = (x-mu)*sqrt(invPsi))
//   maha = |diffs|^2 - |u|^2
//   e_z  = C^-T u
//   term1 = Mt^-1 = C^-T C^-1
//   logdet Sigma = sum log PsiEff + 2 sum log C_kk

#define MCOMP 32
#define NPTS  8192
#define DDIM  64
#define KFAC  16

// ---- scratch (__device__ globals; no allocation allowed) ----
__device__ __align__(16) float g_G2[MCOMP * KFAC * DDIM];   // [m][k][d], row-scaled by s_d
__device__ __align__(16) float g_T[MCOMP * KFAC * KFAC];    // C^-T dense
__device__ __align__(16) float g_t1[MCOMP * KFAC * KFAC];   // Mt^-1
__device__ __align__(16) float g_s[DDIM];                   // sqrt(1/(Psi+1e-6))
__device__ float g_c[MCOMP];                                // log pi - 0.5(D log2pi + logdet)
__device__ __align__(16) float g_logp[NPTS * MCOMP];        // [n][m]

// ============================================================
// Kernel 1: per-component precompute. grid = M blocks, 256 thr
// ============================================================
__global__ __launch_bounds__(256) void precompute_kernel(
    const float* __restrict__ pi,
    const float* __restrict__ Lambda,   // [M][D][K]
    const float* __restrict__ Psi)      // [D]
{
    __shared__ float LamS[DDIM * KFAC];     // [d][k]
    __shared__ float invPsiS[DDIM];
    __shared__ float sS[DDIM];
    __shared__ float MS[KFAC * KFAC];
    __shared__ float CS[KFAC * KFAC];
    __shared__ float CinvS[KFAC * KFAC];
    __shared__ float redS[64];

    const int m = blockIdx.x;
    const int tid = threadIdx.x;

    if (tid < DDIM) {
        float pe = Psi[tid] + 1e-6f;
        float ip = 1.0f / pe;
        invPsiS[tid] = ip;
        sS[tid] = sqrtf(ip);
        redS[tid] = __logf(pe);     // per-dim log for logdet reduction
    }
    for (int idx = tid; idx < DDIM * KFAC; idx += 256)
        LamS[idx] = Lambda[m * DDIM * KFAC + idx];
    __syncthreads();

    if (m == 0 && tid < DDIM) g_s[tid] = sS[tid];

    // Mt = I + Lam^T diag(invPsi) Lam
    {
        int i = tid >> 4, j = tid & 15;
        float acc = (i == j) ? 1.0f : 0.0f;
        #pragma unroll 8
        for (int d = 0; d < DDIM; d++)
            acc = fmaf(LamS[d * KFAC + i] * invPsiS[d], LamS[d * KFAC + j], acc);
        MS[tid] = acc;
    }
    __syncthreads();

    // Cholesky of Mt (KxK), lower C
    for (int jj = 0; jj < KFAC; jj++) {
        if (tid == 0) CS[jj * KFAC + jj] = sqrtf(MS[jj * KFAC + jj]);
        __syncthreads();
        if (tid > jj && tid < KFAC)
            CS[tid * KFAC + jj] = MS[tid * KFAC + jj] / CS[jj * KFAC + jj];
        __syncthreads();
        {
            int a = tid >> 4, b = tid & 15;
            if (a > jj && b > jj && b <= a)
                MS[a * KFAC + b] -= CS[a * KFAC + jj] * CS[b * KFAC + jj];
        }
        __syncthreads();
    }

    // Cinv = C^-1 (lower tri), one column per thread
    if (tid < KFAC) {
        int c = tid;
        float x[KFAC];
        #pragma unroll
        for (int i = 0; i < KFAC; i++) {
            float v = (i == c) ? 1.0f : 0.0f;
            for (int k = c; k < i; k++) v -= CS[i * KFAC + k] * x[k];
            x[i] = (i >= c) ? v / CS[i * KFAC + i] : 0.0f;
        }
        #pragma unroll
        for (int i = 0; i < KFAC; i++) CinvS[i * KFAC + c] = x[i];
    }
    __syncthreads();

    // term1 = Cinv^T Cinv ; T = Cinv^T (dense)
    {
        int i = tid >> 4, j = tid & 15;
        float acc = 0.0f;
        #pragma unroll
        for (int k = 0; k < KFAC; k++)
            acc = fmaf(CinvS[k * KFAC + i], CinvS[k * KFAC + j], acc);
        g_t1[m * 256 + tid] = acc;
        g_T[m * 256 + tid] = CinvS[j * KFAC + i];
    }

    // G2[i][d] = (sum_{k<=i} Cinv[i][k] Lam[d][k]) * s_d
    for (int idx = tid; idx < KFAC * DDIM; idx += 256) {
        int i = idx >> 6, d = idx & 63;
        float acc = 0.0f;
        for (int k = 0; k <= i; k++)
            acc = fmaf(CinvS[i * KFAC + k], LamS[d * KFAC + k], acc);
        g_G2[m * KFAC * DDIM + idx] = acc * sS[d];
    }

    // parallel logdet reduction: redS holds log(PsiEff); add 2*log(C_kk) from lanes 0..15
    if (tid < KFAC) redS[tid] += 2.0f * __logf(CS[tid * KFAC + tid]);
    __syncthreads();
    if (tid < 32) {
        float v = redS[tid] + redS[tid + 32];
        #pragma unroll
        for (int o = 16; o > 0; o >>= 1)
            v += __shfl_down_sync(0xFFFFFFFFu, v, o);
        if (tid == 0) {
            const float LOG2PI = 1.8378770664093453f;
            g_c[m] = __logf(pi[m] + 1e-10f) - 0.5f * (64.0f * LOG2PI + v);
        }
    }
}

// ============================================================
// Kernel 2: main. grid = (N/128, M), 128 threads, 1 point/thread
// ============================================================
__global__ __launch_bounds__(128) void main_kernel(
    const float* __restrict__ X,    // [N][D]
    const float* __restrict__ mu,   // [M][D]
    float* __restrict__ out)
{
    __shared__ float4 Xs4[16 * 129];   // [d4][n], padded rows (33,024 B)
    __shared__ float4 G2s[256];        // [k][d4]
    __shared__ float4 Ts[64];          // [i][j4]
    __shared__ float4 t1s[64];         // [i][j4]
    __shared__ float4 mus[16];
    __shared__ float4 ss4[16];
    __shared__ float4 ezs4[4 * 128];   // [i4][n]  (ez staged for coalesced output)

    const int m = blockIdx.y;
    const int nb = blockIdx.x * 128;
    const int tid = threadIdx.x;

    // per-m constants
    G2s[tid]       = ((const float4*)g_G2)[m * 256 + tid];
    G2s[tid + 128] = ((const float4*)g_G2)[m * 256 + tid + 128];
    if (tid < 64)  Ts[tid]  = ((const float4*)g_T)[m * 64 + tid];
    if (tid >= 64) t1s[tid - 64] = ((const float4*)g_t1)[m * 64 + (tid - 64)];
    if (tid < 16) {
        mus[tid] = ((const float4*)mu)[m * 16 + tid];
        ss4[tid] = ((const float4*)g_s)[tid];
    }
    __syncthreads();

    // stage diffs = (x - mu) * s into smem, [d4][n]
    const float4* Xg = (const float4*)X;
    #pragma unroll
    for (int it = 0; it < 16; it++) {
        int idx = tid + it * 128;          // 0..2047
        int n  = idx >> 4;
        int d4 = idx & 15;
        float4 x = Xg[nb * 16 + idx];      // coalesced
        float4 mu4 = mus[d4], s4 = ss4[d4];
        float4 r;
        r.x = (x.x - mu4.x) * s4.x;
        r.y = (x.y - mu4.y) * s4.y;
        r.z = (x.z - mu4.z) * s4.z;
        r.w = (x.w - mu4.w) * s4.w;
        Xs4[d4 * 129 + n] = r;
    }
    __syncthreads();

    // u = G2 * diffs ; q = |diffs|^2
    float q = 0.0f;
    float u[KFAC];
    #pragma unroll
    for (int k = 0; k < KFAC; k++) u[k] = 0.0f;

    #pragma unroll 4
    for (int d4 = 0; d4 < 16; d4++) {
        float4 xv = Xs4[d4 * 129 + tid];
        q = fmaf(xv.x, xv.x, q);
        q = fmaf(xv.y, xv.y, q);
        q = fmaf(xv.z, xv.z, q);
        q = fmaf(xv.w, xv.w, q);
        #pragma unroll
        for (int k = 0; k < KFAC; k++) {
            float4 g = G2s[k * 16 + d4];   // broadcast
            u[k] = fmaf(g.x, xv.x, u[k]);
            u[k] = fmaf(g.y, xv.y, u[k]);
            u[k] = fmaf(g.z, xv.z, u[k]);
            u[k] = fmaf(g.w, xv.w, u[k]);
        }
    }

    float uu = 0.0f;
    #pragma unroll
    for (int k = 0; k < KFAC; k++) uu = fmaf(u[k], u[k], uu);
    float maha = q - uu;

    const int n = nb + tid;
    g_logp[n * MCOMP + m] = g_c[m] - 0.5f * maha;

    // e_z = T u, staged to smem as [i4][n] (STS.128 per lane, stride 128 -> conflict-free)
    #pragma unroll
    for (int i4 = 0; i4 < 4; i4++) {
        float4 r;
        #pragma unroll
        for (int c = 0; c < 4; c++) {
            int i = i4 * 4 + c;
            float acc = 0.0f;
            #pragma unroll
            for (int j4 = 0; j4 < 4; j4++) {
                float4 t = Ts[i * 4 + j4];
                acc = fmaf(t.x, u[j4 * 4 + 0], acc);
                acc = fmaf(t.y, u[j4 * 4 + 1], acc);
                acc = fmaf(t.z, u[j4 * 4 + 2], acc);
                acc = fmaf(t.w, u[j4 * 4 + 3], acc);
            }
            ((float*)&r)[c] = acc;
        }
        ezs4[i4 * 128 + tid] = r;
    }
    __syncthreads();

    float4* out4 = (float4*)out;
    const long long pairbase = (long long)m * NPTS + nb;   // in points

    // e_z out: base = N*M floats = 65536 float4; tile = 512 float4, coalesced
    {
        float4* dst = out4 + 65536LL + pairbase * 4;
        #pragma unroll
        for (int it = 0; it < 4; it++) {
            int idx = it * 128 + tid;
            int nl = idx >> 2, j4 = idx & 3;
            __stcs(&dst[idx], ezs4[j4 * 128 + nl]);
        }
    }

    // e_zz out: base = (N*M + M*N*K) floats = 1114112 float4; tile = 8192 float4, coalesced
    {
        float4* dst = out4 + 1114112LL + pairbase * 64;
        const float* ezsS = (const float*)ezs4;
        #pragma unroll
        for (int it = 0; it < 64; it++) {
            int idx = it * 128 + tid;
            int nl = idx >> 6;          // uniform per warp
            int qq = idx & 63;
            int i  = qq >> 2, j4 = qq & 3;
            // ez[i] of point nl: ezs4[(i>>2)*128 + nl] component (i&3)
            float e = ezsS[((i >> 2) * 128 + nl) * 4 + (i & 3)];
            float4 ej = ezs4[j4 * 128 + nl];
            float4 t1 = t1s[qq];
            float4 r;
            r.x = fmaf(e, ej.x, t1.x);
            r.y = fmaf(e, ej.y, t1.y);
            r.z = fmaf(e, ej.z, t1.z);
            r.w = fmaf(e, ej.w, t1.w);
            __stcs(&dst[idx], r);
        }
    }
}

// ============================================================
// Kernel 3: softmax over m -> responsibilities [N][M]
// ============================================================
__global__ __launch_bounds__(256) void softmax_kernel(float* __restrict__ out)
{
    const int n = blockIdx.x * 256 + threadIdx.x;
    if (n >= NPTS) return;
    const float4* lp4 = ((const float4*)g_logp) + n * 8;
    float v[32];
    #pragma unroll
    for (int j = 0; j < 8; j++) {
        float4 a = lp4[j];
        v[j * 4 + 0] = a.x; v[j * 4 + 1] = a.y;
        v[j * 4 + 2] = a.z; v[j * 4 + 3] = a.w;
    }
    float mx = v[0];
    #pragma unroll
    for (int i = 1; i < 32; i++) mx = fmaxf(mx, v[i]);
    float s = 0.0f;
    #pragma unroll
    for (int i = 0; i < 32; i++) { v[i] = __expf(v[i] - mx); s += v[i]; }
    float inv = 1.0f / s;
    float4* o4 = ((float4*)out) + n * 8;
    #pragma unroll
    for (int j = 0; j < 8; j++) {
        float4 r;
        r.x = v[j * 4 + 0] * inv;
        r.y = v[j * 4 + 1] * inv;
        r.z = v[j * 4 + 2] * inv;
        r.w = v[j * 4 + 3] * inv;
        o4[j] = r;
    }
}

// ============================================================
extern "C" void kernel_launch(void* const* d_in, const int* in_sizes, int n_in,
                              void* d_out, int out_size)
{
    (void)in_sizes; (void)n_in; (void)out_size;
    const float* X      = (const float*)d_in[0];   // [N,D]
    const float* pi     = (const float*)d_in[1];   // [M]
    const float* mu     = (const float*)d_in[2];   // [M,D]
    const float* Lambda = (const float*)d_in[3];   // [M,D,K]
    const float* Psi    = (const float*)d_in[4];   // [D]
    float* out = (float*)d_out;

    precompute_kernel<<<MCOMP, 256>>>(pi, Lambda, Psi);
    main_kernel<<<dim3(NPTS / 128, MCOMP), 128>>>(X, mu, out);
    softmax_kernel<<<NPTS / 256, 256>>>(out);
}

// round 5
// speedup vs baseline: 2.5031x; 1.0660x over previous
#include <cuda_runtime.h>
#include <math.h>

// MFA E-step: M=32 components, N=8192 points, D=64 dims, K=16 factors.
// Woodbury: Sigma^-1 = Psi^-1 - Psi^-1 L (I + L^T Psi^-1 L)^-1 L^T Psi^-1
//   Mt = I + L^T Psi^-1 L (KxK),  C = chol(Mt)
//   u = C^-1 L^T Psi^-1 diff   (via G2 * diffs, diffs = (x-mu)*sqrt(invPsi))
//   maha = |diffs|^2 - |u|^2
//   e_z  = C^-T u
//   term1 = Mt^-1 = C^-T C^-1
//   logdet Sigma = sum log PsiEff + 2 sum log C_kk

#define MCOMP 32
#define NPTS  8192
#define DDIM  64
#define KFAC  16

// ---- scratch (__device__ globals; no allocation allowed) ----
__device__ __align__(16) float g_G2[MCOMP * KFAC * DDIM];   // [m][k][d], row-scaled by s_d
__device__ __align__(16) float g_T[MCOMP * KFAC * KFAC];    // C^-T dense
__device__ __align__(16) float g_t1[MCOMP * KFAC * KFAC];   // Mt^-1
__device__ __align__(16) float g_s[DDIM];                   // sqrt(1/(Psi+1e-6))
__device__ float g_c[MCOMP];                                // log pi - 0.5(D log2pi + logdet)
__device__ __align__(16) float g_logp[NPTS * MCOMP];        // [n][m]

// ============================================================
// Kernel 1: per-component precompute. grid = M blocks, 128 thr
// Warp 0 does the tiny KxK Cholesky/inverse (register-resident,
// fully unrolled, no local memory, no block barriers inside).
// ============================================================
__global__ __launch_bounds__(128) void precompute_kernel(
    const float* __restrict__ pi,
    const float* __restrict__ Lambda,   // [M][D][K]
    const float* __restrict__ Psi)      // [D]
{
    __shared__ float LamS[DDIM * KFAC];     // [d][k]
    __shared__ float invPsiS[DDIM];
    __shared__ float sS[DDIM];
    __shared__ float MS[KFAC * KFAC];
    __shared__ float CS[KFAC * KFAC];
    __shared__ float CinvS[KFAC * KFAC];
    __shared__ float redS[64];

    const int m = blockIdx.x;
    const int tid = threadIdx.x;
    const int lane = tid & 31;

    if (tid < DDIM) {
        float pe = Psi[tid] + 1e-6f;
        float ip = 1.0f / pe;
        invPsiS[tid] = ip;
        sS[tid] = sqrtf(ip);
        redS[tid] = __logf(pe);     // per-dim log for logdet reduction
    }
    // Lam: 256 float4 / 128 threads = 2 each
    {
        const float4* Lg = (const float4*)(Lambda + m * DDIM * KFAC);
        ((float4*)LamS)[tid]       = Lg[tid];
        ((float4*)LamS)[tid + 128] = Lg[tid + 128];
    }
    __syncthreads();

    if (m == 0 && tid < DDIM) g_s[tid] = sS[tid];

    // Mt = I + Lam^T diag(invPsi) Lam : 256 entries / 128 threads = 2 each
    #pragma unroll
    for (int e = 0; e < 2; e++) {
        int idx = tid + e * 128;
        int i = idx >> 4, j = idx & 15;
        float acc = (i == j) ? 1.0f : 0.0f;
        #pragma unroll 8
        for (int d = 0; d < DDIM; d++)
            acc = fmaf(LamS[d * KFAC + i] * invPsiS[d], LamS[d * KFAC + j], acc);
        MS[idx] = acc;
    }
    __syncthreads();

    // --- warp 0: Cholesky of Mt (lower C), then Cinv = C^-1 ---
    if (tid < 32) {
        #pragma unroll
        for (int jj = 0; jj < KFAC; jj++) {
            if (lane == 0) CS[jj * KFAC + jj] = sqrtf(MS[jj * KFAC + jj]);
            __syncwarp();
            float rdiag = __fdividef(1.0f, CS[jj * KFAC + jj]);
            if (lane > jj && lane < KFAC)
                CS[lane * KFAC + jj] = MS[lane * KFAC + jj] * rdiag;
            __syncwarp();
            #pragma unroll
            for (int e = 0; e < 8; e++) {
                int idx = lane + e * 32;
                int a = idx >> 4, b = idx & 15;
                if (a > jj && b > jj && b <= a)
                    MS[a * KFAC + b] -= CS[a * KFAC + jj] * CS[b * KFAC + jj];
            }
            __syncwarp();
        }

        // Cinv column c = lane (lanes 0..15). Fully unrolled; x[] in regs.
        // For i < c: v stays 0 -> x[i]=0 automatically (zero-padded recurrence).
        if (lane < KFAC) {
            const int c = lane;
            float x[KFAC];
            #pragma unroll
            for (int i = 0; i < KFAC; i++) {
                float v = (i == c) ? 1.0f : 0.0f;
                #pragma unroll
                for (int k = 0; k < KFAC; k++) {
                    if (k < i) v = fmaf(-CS[i * KFAC + k], x[k], v);
                }
                x[i] = v * __fdividef(1.0f, CS[i * KFAC + i]);
            }
            #pragma unroll
            for (int i = 0; i < KFAC; i++) CinvS[i * KFAC + c] = x[i];
        }
    }
    __syncthreads();

    // term1 = Cinv^T Cinv ; T = Cinv^T (dense) : 2 entries per thread
    #pragma unroll
    for (int e = 0; e < 2; e++) {
        int idx = tid + e * 128;
        int i = idx >> 4, j = idx & 15;
        float acc = 0.0f;
        #pragma unroll
        for (int k = 0; k < KFAC; k++)
            acc = fmaf(CinvS[k * KFAC + i], CinvS[k * KFAC + j], acc);
        g_t1[m * 256 + idx] = acc;
        g_T[m * 256 + idx] = CinvS[j * KFAC + i];
    }

    // G2[i][d] = (sum_{k<=i} Cinv[i][k] Lam[d][k]) * s_d : 8 per thread
    #pragma unroll
    for (int e = 0; e < 8; e++) {
        int idx = tid + e * 128;
        int i = idx >> 6, d = idx & 63;
        float acc = 0.0f;
        #pragma unroll
        for (int k = 0; k < KFAC; k++) {
            if (k <= i) acc = fmaf(CinvS[i * KFAC + k], LamS[d * KFAC + k], acc);
        }
        g_G2[m * KFAC * DDIM + idx] = acc * sS[d];
    }

    // logdet reduction: redS holds log(PsiEff); add 2*log(C_kk) from lanes 0..15
    if (tid < KFAC) redS[tid] += 2.0f * __logf(CS[tid * KFAC + tid]);
    __syncthreads();
    if (tid < 32) {
        float v = redS[tid] + redS[tid + 32];
        #pragma unroll
        for (int o = 16; o > 0; o >>= 1)
            v += __shfl_down_sync(0xFFFFFFFFu, v, o);
        if (tid == 0) {
            const float LOG2PI = 1.8378770664093453f;
            g_c[m] = __logf(pi[m] + 1e-10f) - 0.5f * (64.0f * LOG2PI + v);
        }
    }
}

// ============================================================
// Kernel 2: main. grid = (N/128, M), 128 threads, 1 point/thread
// ============================================================
__global__ __launch_bounds__(128) void main_kernel(
    const float* __restrict__ X,    // [N][D]
    const float* __restrict__ mu,   // [M][D]
    float* __restrict__ out)
{
    __shared__ float4 Xs4[16 * 129];   // [d4][n], padded rows (33,024 B)
    __shared__ float4 G2s[256];        // [k][d4]
    __shared__ float4 Ts[64];          // [i][j4]
    __shared__ float4 t1s[64];         // [i][j4]
    __shared__ float4 mus[16];
    __shared__ float4 ss4[16];
    __shared__ float4 ezs4[4 * 128];   // [i4][n]  (ez staged for coalesced output)

    const int m = blockIdx.y;
    const int nb = blockIdx.x * 128;
    const int tid = threadIdx.x;

    // per-m constants
    G2s[tid]       = ((const float4*)g_G2)[m * 256 + tid];
    G2s[tid + 128] = ((const float4*)g_G2)[m * 256 + tid + 128];
    if (tid < 64)  Ts[tid]  = ((const float4*)g_T)[m * 64 + tid];
    if (tid >= 64) t1s[tid - 64] = ((const float4*)g_t1)[m * 64 + (tid - 64)];
    if (tid < 16) {
        mus[tid] = ((const float4*)mu)[m * 16 + tid];
        ss4[tid] = ((const float4*)g_s)[tid];
    }
    __syncthreads();

    // stage diffs = (x - mu) * s into smem, [d4][n]
    const float4* Xg = (const float4*)X;
    #pragma unroll
    for (int it = 0; it < 16; it++) {
        int idx = tid + it * 128;          // 0..2047
        int n  = idx >> 4;
        int d4 = idx & 15;
        float4 x = Xg[nb * 16 + idx];      // coalesced
        float4 mu4 = mus[d4], s4 = ss4[d4];
        float4 r;
        r.x = (x.x - mu4.x) * s4.x;
        r.y = (x.y - mu4.y) * s4.y;
        r.z = (x.z - mu4.z) * s4.z;
        r.w = (x.w - mu4.w) * s4.w;
        Xs4[d4 * 129 + n] = r;
    }
    __syncthreads();

    // u = G2 * diffs ; q = |diffs|^2
    float q = 0.0f;
    float u[KFAC];
    #pragma unroll
    for (int k = 0; k < KFAC; k++) u[k] = 0.0f;

    #pragma unroll 4
    for (int d4 = 0; d4 < 16; d4++) {
        float4 xv = Xs4[d4 * 129 + tid];
        q = fmaf(xv.x, xv.x, q);
        q = fmaf(xv.y, xv.y, q);
        q = fmaf(xv.z, xv.z, q);
        q = fmaf(xv.w, xv.w, q);
        #pragma unroll
        for (int k = 0; k < KFAC; k++) {
            float4 g = G2s[k * 16 + d4];   // broadcast
            u[k] = fmaf(g.x, xv.x, u[k]);
            u[k] = fmaf(g.y, xv.y, u[k]);
            u[k] = fmaf(g.z, xv.z, u[k]);
            u[k] = fmaf(g.w, xv.w, u[k]);
        }
    }

    float uu = 0.0f;
    #pragma unroll
    for (int k = 0; k < KFAC; k++) uu = fmaf(u[k], u[k], uu);
    float maha = q - uu;

    const int n = nb + tid;
    g_logp[n * MCOMP + m] = g_c[m] - 0.5f * maha;

    // e_z = T u, staged to smem as [i4][n] (STS.128 per lane, stride 128 -> conflict-free)
    #pragma unroll
    for (int i4 = 0; i4 < 4; i4++) {
        float4 r;
        #pragma unroll
        for (int c = 0; c < 4; c++) {
            int i = i4 * 4 + c;
            float acc = 0.0f;
            #pragma unroll
            for (int j4 = 0; j4 < 4; j4++) {
                float4 t = Ts[i * 4 + j4];
                acc = fmaf(t.x, u[j4 * 4 + 0], acc);
                acc = fmaf(t.y, u[j4 * 4 + 1], acc);
                acc = fmaf(t.z, u[j4 * 4 + 2], acc);
                acc = fmaf(t.w, u[j4 * 4 + 3], acc);
            }
            ((float*)&r)[c] = acc;
        }
        ezs4[i4 * 128 + tid] = r;
    }
    __syncthreads();

    float4* out4 = (float4*)out;
    const long long pairbase = (long long)m * NPTS + nb;   // in points

    // e_z out: base = N*M floats = 65536 float4; tile = 512 float4, coalesced
    {
        float4* dst = out4 + 65536LL + pairbase * 4;
        #pragma unroll
        for (int it = 0; it < 4; it++) {
            int idx = it * 128 + tid;
            int nl = idx >> 2, j4 = idx & 3;
            __stcs(&dst[idx], ezs4[j4 * 128 + nl]);
        }
    }

    // e_zz out: base = (N*M + M*N*K) floats = 1114112 float4; tile = 8192 float4, coalesced
    {
        float4* dst = out4 + 1114112LL + pairbase * 64;
        const float* ezsS = (const float*)ezs4;
        #pragma unroll
        for (int it = 0; it < 64; it++) {
            int idx = it * 128 + tid;
            int nl = idx >> 6;          // uniform per warp
            int qq = idx & 63;
            int i  = qq >> 2, j4 = qq & 3;
            float e = ezsS[((i >> 2) * 128 + nl) * 4 + (i & 3)];
            float4 ej = ezs4[j4 * 128 + nl];
            float4 t1 = t1s[qq];
            float4 r;
            r.x = fmaf(e, ej.x, t1.x);
            r.y = fmaf(e, ej.y, t1.y);
            r.z = fmaf(e, ej.z, t1.z);
            r.w = fmaf(e, ej.w, t1.w);
            __stcs(&dst[idx], r);
        }
    }
}

// ============================================================
// Kernel 3: softmax over m -> responsibilities [N][M]
// Warp-per-point: lane m handles component m. Fully coalesced.
// ============================================================
__global__ __launch_bounds__(256) void softmax_kernel(float* __restrict__ out)
{
    const int warp = (blockIdx.x * 256 + threadIdx.x) >> 5;   // point index
    const int lane = threadIdx.x & 31;
    if (warp >= NPTS) return;

    float v = g_logp[warp * MCOMP + lane];
    float mx = v;
    #pragma unroll
    for (int o = 16; o > 0; o >>= 1)
        mx = fmaxf(mx, __shfl_xor_sync(0xFFFFFFFFu, mx, o));
    float e = __expf(v - mx);
    float s = e;
    #pragma unroll
    for (int o = 16; o > 0; o >>= 1)
        s += __shfl_xor_sync(0xFFFFFFFFu, s, o);
    out[warp * MCOMP + lane] = e * __fdividef(1.0f, s);
}

// ============================================================
extern "C" void kernel_launch(void* const* d_in, const int* in_sizes, int n_in,
                              void* d_out, int out_size)
{
    (void)in_sizes; (void)n_in; (void)out_size;
    const float* X      = (const float*)d_in[0];   // [N,D]
    const float* pi     = (const float*)d_in[1];   // [M]
    const float* mu     = (const float*)d_in[2];   // [M,D]
    const float* Lambda = (const float*)d_in[3];   // [M,D,K]
    const float* Psi    = (const float*)d_in[4];   // [D]
    float* out = (float*)d_out;

    precompute_kernel<<<MCOMP, 128>>>(pi, Lambda, Psi);
    main_kernel<<<dim3(NPTS / 128, MCOMP), 128>>>(X, mu, out);
    softmax_kernel<<<NPTS / 8, 256>>>(out);   // 8 points per block (256 thr = 8 warps)
}

// round 7
// speedup vs baseline: 2.7359x; 1.0930x over previous
#include <cuda_runtime.h>
#include <math.h>

// MFA E-step: M=32 components, N=8192 points, D=64 dims, K=16 factors.
// Woodbury: Sigma^-1 = Psi^-1 - Psi^-1 L (I + L^T Psi^-1 L)^-1 L^T Psi^-1
//   Mt = I + L^T Psi^-1 L (KxK),  C = chol(Mt)
//   u = C^-1 L^T Psi^-1 diff   (via G2 * diffs, diffs = (x-mu)*sqrt(invPsi))
//   maha = |diffs|^2 - |u|^2
//   e_z  = C^-T u
//   term1 = Mt^-1 = C^-T C^-1
//   logdet Sigma = sum log PsiEff + 2 sum log C_kk
//
// Pipeline: precompute -> ez_kernel (logp + e_z) -> ezz_kernel (stream) -> softmax

#define MCOMP 32
#define NPTS  8192
#define DDIM  64
#define KFAC  16

// ---- scratch (__device__ globals; no allocation allowed) ----
__device__ __align__(16) float g_G2[MCOMP * KFAC * DDIM];   // [m][k][d], row-scaled by s_d
__device__ __align__(16) float g_T[MCOMP * KFAC * KFAC];    // C^-T dense
__device__ __align__(16) float g_t1[MCOMP * KFAC * KFAC];   // Mt^-1
__device__ __align__(16) float g_s[DDIM];                   // sqrt(1/(Psi+1e-6))
__device__ float g_c[MCOMP];                                // log pi - 0.5(D log2pi + logdet)
__device__ __align__(16) float g_logp[NPTS * MCOMP];        // [n][m]

// ============================================================
// Kernel 1: per-component precompute. grid = M blocks, 128 thr
// ============================================================
__global__ __launch_bounds__(128) void precompute_kernel(
    const float* __restrict__ pi,
    const float* __restrict__ Lambda,   // [M][D][K]
    const float* __restrict__ Psi)      // [D]
{
    __shared__ float LamS[DDIM * KFAC];     // [d][k]
    __shared__ float invPsiS[DDIM];
    __shared__ float sS[DDIM];
    __shared__ float MS[KFAC * KFAC];
    __shared__ float CS[KFAC * KFAC];
    __shared__ float CinvS[KFAC * KFAC];
    __shared__ float redS[64];

    const int m = blockIdx.x;
    const int tid = threadIdx.x;
    const int lane = tid & 31;

    if (tid < DDIM) {
        float pe = Psi[tid] + 1e-6f;
        float ip = 1.0f / pe;
        invPsiS[tid] = ip;
        sS[tid] = sqrtf(ip);
        redS[tid] = __logf(pe);
    }
    {
        const float4* Lg = (const float4*)(Lambda + m * DDIM * KFAC);
        ((float4*)LamS)[tid]       = Lg[tid];
        ((float4*)LamS)[tid + 128] = Lg[tid + 128];
    }
    __syncthreads();

    if (m == 0 && tid < DDIM) g_s[tid] = sS[tid];

    // Mt = I + Lam^T diag(invPsi) Lam
    #pragma unroll
    for (int e = 0; e < 2; e++) {
        int idx = tid + e * 128;
        int i = idx >> 4, j = idx & 15;
        float acc = (i == j) ? 1.0f : 0.0f;
        #pragma unroll 8
        for (int d = 0; d < DDIM; d++)
            acc = fmaf(LamS[d * KFAC + i] * invPsiS[d], LamS[d * KFAC + j], acc);
        MS[idx] = acc;
    }
    __syncthreads();

    // --- warp 0: Cholesky of Mt (lower C), then Cinv = C^-1 ---
    if (tid < 32) {
        #pragma unroll
        for (int jj = 0; jj < KFAC; jj++) {
            if (lane == 0) CS[jj * KFAC + jj] = sqrtf(MS[jj * KFAC + jj]);
            __syncwarp();
            float rdiag = __fdividef(1.0f, CS[jj * KFAC + jj]);
            if (lane > jj && lane < KFAC)
                CS[lane * KFAC + jj] = MS[lane * KFAC + jj] * rdiag;
            __syncwarp();
            #pragma unroll
            for (int e = 0; e < 8; e++) {
                int idx = lane + e * 32;
                int a = idx >> 4, b = idx & 15;
                if (a > jj && b > jj && b <= a)
                    MS[a * KFAC + b] -= CS[a * KFAC + jj] * CS[b * KFAC + jj];
            }
            __syncwarp();
        }

        if (lane < KFAC) {
            const int c = lane;
            float x[KFAC];
            #pragma unroll
            for (int i = 0; i < KFAC; i++) {
                float v = (i == c) ? 1.0f : 0.0f;
                #pragma unroll
                for (int k = 0; k < KFAC; k++) {
                    if (k < i) v = fmaf(-CS[i * KFAC + k], x[k], v);
                }
                x[i] = v * __fdividef(1.0f, CS[i * KFAC + i]);
            }
            #pragma unroll
            for (int i = 0; i < KFAC; i++) CinvS[i * KFAC + c] = x[i];
        }
    }
    __syncthreads();

    // term1 = Cinv^T Cinv ; T = Cinv^T (dense)
    #pragma unroll
    for (int e = 0; e < 2; e++) {
        int idx = tid + e * 128;
        int i = idx >> 4, j = idx & 15;
        float acc = 0.0f;
        #pragma unroll
        for (int k = 0; k < KFAC; k++)
            acc = fmaf(CinvS[k * KFAC + i], CinvS[k * KFAC + j], acc);
        g_t1[m * 256 + idx] = acc;
        g_T[m * 256 + idx] = CinvS[j * KFAC + i];
    }

    // G2[i][d] = (sum_{k<=i} Cinv[i][k] Lam[d][k]) * s_d
    #pragma unroll
    for (int e = 0; e < 8; e++) {
        int idx = tid + e * 128;
        int i = idx >> 6, d = idx & 63;
        float acc = 0.0f;
        #pragma unroll
        for (int k = 0; k < KFAC; k++) {
            if (k <= i) acc = fmaf(CinvS[i * KFAC + k], LamS[d * KFAC + k], acc);
        }
        g_G2[m * KFAC * DDIM + idx] = acc * sS[d];
    }

    if (tid < KFAC) redS[tid] += 2.0f * __logf(CS[tid * KFAC + tid]);
    __syncthreads();
    if (tid < 32) {
        float v = redS[tid] + redS[tid + 32];
        #pragma unroll
        for (int o = 16; o > 0; o >>= 1)
            v += __shfl_down_sync(0xFFFFFFFFu, v, o);
        if (tid == 0) {
            const float LOG2PI = 1.8378770664093453f;
            g_c[m] = __logf(pi[m] + 1e-10f) - 0.5f * (64.0f * LOG2PI + v);
        }
    }
}

// ============================================================
// Kernel 2a: logp + e_z. grid = (N/128, M), 64 threads,
// 2 points per thread (amortizes G2 broadcast LDS over 2 pts).
// ============================================================
__global__ __launch_bounds__(64) void ez_kernel(
    const float* __restrict__ X,    // [N][D]
    const float* __restrict__ mu,   // [M][D]
    float* __restrict__ out)
{
    __shared__ float4 Xs4[16 * 129];   // [d4][n], padded (33,024 B)
    __shared__ float4 G2s[256];        // [k][d4]
    __shared__ float4 Ts[64];          // [i][j4]
    __shared__ float4 mus[16];
    __shared__ float4 ss4[16];
    __shared__ float4 ezs4[4 * 128];   // [i4][n]

    const int m = blockIdx.y;
    const int nb = blockIdx.x * 128;
    const int tid = threadIdx.x;

    #pragma unroll
    for (int e = 0; e < 4; e++)
        G2s[tid + e * 64] = ((const float4*)g_G2)[m * 256 + tid + e * 64];
    Ts[tid] = ((const float4*)g_T)[m * 64 + tid];
    if (tid < 16) {
        mus[tid] = ((const float4*)mu)[m * 16 + tid];
        ss4[tid] = ((const float4*)g_s)[tid];
    }
    __syncthreads();

    // stage diffs = (x - mu) * s into smem, [d4][n]
    const float4* Xg = (const float4*)X;
    #pragma unroll
    for (int it = 0; it < 32; it++) {
        int idx = tid + it * 64;           // 0..2047
        int n  = idx >> 4;
        int d4 = idx & 15;
        float4 x = Xg[nb * 16 + idx];      // coalesced
        float4 mu4 = mus[d4], s4 = ss4[d4];
        float4 r;
        r.x = (x.x - mu4.x) * s4.x;
        r.y = (x.y - mu4.y) * s4.y;
        r.z = (x.z - mu4.z) * s4.z;
        r.w = (x.w - mu4.w) * s4.w;
        Xs4[d4 * 129 + n] = r;
    }
    __syncthreads();

    // two points per thread: n0 = nb+tid, n1 = nb+tid+64
    float q0 = 0.0f, q1 = 0.0f;
    float u0[KFAC], u1[KFAC];
    #pragma unroll
    for (int k = 0; k < KFAC; k++) { u0[k] = 0.0f; u1[k] = 0.0f; }

    #pragma unroll 4
    for (int d4 = 0; d4 < 16; d4++) {
        float4 a = Xs4[d4 * 129 + tid];
        float4 b = Xs4[d4 * 129 + tid + 64];
        q0 = fmaf(a.x, a.x, q0); q0 = fmaf(a.y, a.y, q0);
        q0 = fmaf(a.z, a.z, q0); q0 = fmaf(a.w, a.w, q0);
        q1 = fmaf(b.x, b.x, q1); q1 = fmaf(b.y, b.y, q1);
        q1 = fmaf(b.z, b.z, q1); q1 = fmaf(b.w, b.w, q1);
        #pragma unroll
        for (int k = 0; k < KFAC; k++) {
            float4 g = G2s[k * 16 + d4];   // broadcast, shared by both points
            u0[k] = fmaf(g.x, a.x, u0[k]);
            u0[k] = fmaf(g.y, a.y, u0[k]);
            u0[k] = fmaf(g.z, a.z, u0[k]);
            u0[k] = fmaf(g.w, a.w, u0[k]);
            u1[k] = fmaf(g.x, b.x, u1[k]);
            u1[k] = fmaf(g.y, b.y, u1[k]);
            u1[k] = fmaf(g.z, b.z, u1[k]);
            u1[k] = fmaf(g.w, b.w, u1[k]);
        }
    }

    float uu0 = 0.0f, uu1 = 0.0f;
    #pragma unroll
    for (int k = 0; k < KFAC; k++) {
        uu0 = fmaf(u0[k], u0[k], uu0);
        uu1 = fmaf(u1[k], u1[k], uu1);
    }
    const float cm = g_c[m];
    g_logp[(nb + tid) * MCOMP + m]      = cm - 0.5f * (q0 - uu0);
    g_logp[(nb + tid + 64) * MCOMP + m] = cm - 0.5f * (q1 - uu1);

    // e_z = T u for both points, staged to [i4][n]
    #pragma unroll
    for (int i4 = 0; i4 < 4; i4++) {
        float4 r0, r1;
        #pragma unroll
        for (int c = 0; c < 4; c++) {
            int i = i4 * 4 + c;
            float a0 = 0.0f, a1 = 0.0f;
            #pragma unroll
            for (int j4 = 0; j4 < 4; j4++) {
                float4 t = Ts[i * 4 + j4];
                a0 = fmaf(t.x, u0[j4 * 4 + 0], a0);
                a0 = fmaf(t.y, u0[j4 * 4 + 1], a0);
                a0 = fmaf(t.z, u0[j4 * 4 + 2], a0);
                a0 = fmaf(t.w, u0[j4 * 4 + 3], a0);
                a1 = fmaf(t.x, u1[j4 * 4 + 0], a1);
                a1 = fmaf(t.y, u1[j4 * 4 + 1], a1);
                a1 = fmaf(t.z, u1[j4 * 4 + 2], a1);
                a1 = fmaf(t.w, u1[j4 * 4 + 3], a1);
            }
            ((float*)&r0)[c] = a0;
            ((float*)&r1)[c] = a1;
        }
        ezs4[i4 * 128 + tid]      = r0;
        ezs4[i4 * 128 + tid + 64] = r1;
    }
    __syncthreads();

    // coalesced e_z out (plain stores -> stays in L2 for ezz_kernel)
    // base = N*M floats = 65536 float4
    {
        float4* dst = (float4*)out + 65536LL + ((long long)m * NPTS + nb) * 4;
        #pragma unroll
        for (int it = 0; it < 8; it++) {
            int idx = it * 64 + tid;
            int nl = idx >> 2, j4 = idx & 3;
            dst[idx] = ezs4[j4 * 128 + nl];
        }
    }
}

// ============================================================
// Kernel 2b: e_zz = term1 + outer(ez, ez). Pure stream.
// grid = 8192 blocks x 256 thr; each block: 2048 consecutive
// float4 of e_zz (= 32 (m,n) pairs). Reads ez from out (L2-hot).
// ============================================================
__global__ __launch_bounds__(256) void ezz_kernel(float* __restrict__ out)
{
    float4* out4 = (float4*)out;
    const float4* ez4 = (const float4*)out + 65536;   // e_z region
    const float*  ezf = (const float*)ez4;
    const float4* t14 = (const float4*)g_t1;

    const long long base = (long long)blockIdx.x * 2048;
    const int tid = threadIdx.x;

    #pragma unroll
    for (int it = 0; it < 8; it++) {
        long long idx = base + it * 256 + tid;       // float4 index within e_zz
        int p  = (int)(idx >> 6);                    // pair = m*N + n
        int qq = (int)idx & 63;                      // i*4 + j4
        int i  = qq >> 2, j4 = qq & 3;
        int m  = p >> 13;                            // N = 8192

        float  e  = ezf[(long long)p * 16 + i];      // broadcast-ish, L1/L2 hit
        float4 ej = ez4[(long long)p * 4 + j4];      // 4 distinct/warp, L1 hit
        float4 t1 = t14[m * 64 + qq];                // 8KB table, L1-resident

        float4 r;
        r.x = fmaf(e, ej.x, t1.x);
        r.y = fmaf(e, ej.y, t1.y);
        r.z = fmaf(e, ej.z, t1.z);
        r.w = fmaf(e, ej.w, t1.w);
        __stcs(&out4[1114112LL + idx], r);           // e_zz base = 1114112 float4
    }
}

// ============================================================
// Kernel 3: softmax over m -> responsibilities [N][M]
// ============================================================
__global__ __launch_bounds__(256) void softmax_kernel(float* __restrict__ out)
{
    const int warp = (blockIdx.x * 256 + threadIdx.x) >> 5;   // point index
    const int lane = threadIdx.x & 31;
    if (warp >= NPTS) return;

    float v = g_logp[warp * MCOMP + lane];
    float mx = v;
    #pragma unroll
    for (int o = 16; o > 0; o >>= 1)
        mx = fmaxf(mx, __shfl_xor_sync(0xFFFFFFFFu, mx, o));
    float e = __expf(v - mx);
    float s = e;
    #pragma unroll
    for (int o = 16; o > 0; o >>= 1)
        s += __shfl_xor_sync(0xFFFFFFFFu, s, o);
    out[warp * MCOMP + lane] = e * __fdividef(1.0f, s);
}

// ============================================================
extern "C" void kernel_launch(void* const* d_in, const int* in_sizes, int n_in,
                              void* d_out, int out_size)
{
    (void)in_sizes; (void)n_in; (void)out_size;
    const float* X      = (const float*)d_in[0];   // [N,D]
    const float* pi     = (const float*)d_in[1];   // [M]
    const float* mu     = (const float*)d_in[2];   // [M,D]
    const float* Lambda = (const float*)d_in[3];   // [M,D,K]
    const float* Psi    = (const float*)d_in[4];   // [D]
    float* out = (float*)d_out;

    precompute_kernel<<<MCOMP, 128>>>(pi, Lambda, Psi);
    ez_kernel<<<dim3(NPTS / 128, MCOMP), 64>>>(X, mu, out);
    ezz_kernel<<<8192, 256>>>(out);
    softmax_kernel<<<NPTS / 8, 256>>>(out);
}